// round 1
// baseline (speedup 1.0000x reference)
#include <cuda_runtime.h>
#include <math.h>

#define BB    4
#define SSEQ  4096
#define IND   1024
#define OUTD  1024
#define EE    8
#define LSCALE 512.0f

// ---- scratch (device globals; no allocation allowed) ----
__device__ float g_seg[BB * IND];          // 16 KB  : per-batch column sums of x
__device__ float g_h[(size_t)BB * SSEQ * EE]; // 512 KB : all-expert dots (L2 resident)
__device__ float g_coef[BB * 2];
__device__ int   g_idx[BB * 2];

// ------------------------------------------------------------------
// K0: zero the segment accumulator (graph replays re-run atomics)
// ------------------------------------------------------------------
__global__ void k0_zero() {
    int i = blockIdx.x * 256 + threadIdx.x;
    if (i < BB * IND) g_seg[i] = 0.0f;
}

// ------------------------------------------------------------------
// K1: h[b,s,e] = x[b,s,:]·A_e  for all 8 experts, + seg sums.
// grid = 512 blocks (128 per batch, 32 tokens each), 256 threads.
// Warp w handles k-slice [w*16, w*16+16) of each 128-wide k-chunk;
// A is read warp-uniform (broadcast) from shared.
// ------------------------------------------------------------------
#define TT 32           // tokens per block
#define XS_STRIDE 132   // 128 + 4 pad (16B-aligned rows, conflict-free LDS.128)

__global__ void __launch_bounds__(256) k1_dots(const float* __restrict__ x,
                                               const float* __restrict__ lora_A) {
    __shared__ float A_c[128 * 8];          // [k_local][e]   4 KB
    __shared__ float xs[TT * XS_STRIDE];    // [t][k_local]  16.9 KB

    const int tid = threadIdx.x;
    const int b = blockIdx.x >> 7;                // 128 blocks per batch
    const int tokbase = (blockIdx.x & 127) * TT;
    const int g = tid >> 5;                       // warp id = k-group 0..7
    const int t = tid & 31;                       // token within tile

    float acc[8] = {0.f,0.f,0.f,0.f,0.f,0.f,0.f,0.f};
    const float* xbase = x + ((size_t)b * SSEQ + tokbase) * IND;

    for (int c = 0; c < 8; ++c) {                 // 8 k-chunks of 128
        // --- stage A chunk [128][8], coalesced read, transposed store ---
        #pragma unroll
        for (int i = 0; i < 4; ++i) {
            int idx = tid + i * 256;              // 0..1023
            int e = idx >> 7, k = idx & 127;
            A_c[k * 8 + e] = lora_A[e * IND + c * 128 + k];
        }
        // --- stage x tile [32][128] as float4, coalesced ---
        #pragma unroll
        for (int i = 0; i < 4; ++i) {
            int idx = tid + i * 256;              // 0..1023 float4 units
            int row = idx >> 5, c4 = idx & 31;
            float4 v = *(const float4*)(xbase + (size_t)row * IND + c * 128 + c4 * 4);
            *(float4*)&xs[row * XS_STRIDE + c4 * 4] = v;
        }
        __syncthreads();

        // --- compute: this warp's 16 k's of the chunk ---
        const float* xr = &xs[t * XS_STRIDE + g * 16];
        const float* Abase = &A_c[(g * 16) * 8];
        #pragma unroll
        for (int kk = 0; kk < 16; kk += 4) {
            float4 xv = *(const float4*)(xr + kk);
            float xj[4] = {xv.x, xv.y, xv.z, xv.w};
            #pragma unroll
            for (int j = 0; j < 4; ++j) {
                const float* Ak = Abase + (kk + j) * 8;   // warp-uniform
                float4 a0 = *(const float4*)(Ak);
                float4 a1 = *(const float4*)(Ak + 4);
                acc[0] += xj[j] * a0.x;  acc[1] += xj[j] * a0.y;
                acc[2] += xj[j] * a0.z;  acc[3] += xj[j] * a0.w;
                acc[4] += xj[j] * a1.x;  acc[5] += xj[j] * a1.y;
                acc[6] += xj[j] * a1.z;  acc[7] += xj[j] * a1.w;
            }
        }

        // --- segment-sum reduction straight out of the staged tile ---
        {
            int col = tid & 127, half = tid >> 7;       // 2 threads per column
            const float* xc = &xs[(half * 16) * XS_STRIDE + col];
            float s = 0.f;
            #pragma unroll
            for (int r = 0; r < 16; ++r) s += xc[r * XS_STRIDE];
            atomicAdd(&g_seg[b * IND + c * 128 + col], s);
        }
        __syncthreads();
    }

    // --- cross-warp (k-group) reduction via shared (reuse xs) ---
    float* red = xs;                                // 8*32*8 = 2048 floats
    *(float4*)&red[(g * 32 + t) * 8]     = make_float4(acc[0], acc[1], acc[2], acc[3]);
    *(float4*)&red[(g * 32 + t) * 8 + 4] = make_float4(acc[4], acc[5], acc[6], acc[7]);
    __syncthreads();
    {
        int tt = tid >> 3, e = tid & 7;             // 256 threads = 32 tok x 8 e
        float s = 0.f;
        #pragma unroll
        for (int gg = 0; gg < 8; ++gg) s += red[(gg * 32 + tt) * 8 + e];
        g_h[((size_t)b * SSEQ + tokbase + tt) * EE + e] = s;
    }
}

// ------------------------------------------------------------------
// K2: logits = seg_mean·G^T + bias ; softmax ; top-2 ; coefs = 512*w
// ------------------------------------------------------------------
__global__ void k2_gate(const float* __restrict__ gate_w,
                        const float* __restrict__ gate_b) {
    __shared__ float dots[BB * EE];
    int tid = threadIdx.x;                 // 1024 threads
    int pair = tid >> 5, lane = tid & 31;  // 32 (b,e) pairs, one warp each
    int b = pair >> 3, e = pair & 7;
    float s = 0.f;
    for (int k = lane; k < IND; k += 32)
        s += g_seg[b * IND + k] * gate_w[e * IND + k];
    #pragma unroll
    for (int o = 16; o; o >>= 1) s += __shfl_xor_sync(0xffffffffu, s, o);
    if (lane == 0) dots[pair] = s * (1.0f / (float)SSEQ) + gate_b[e];
    __syncthreads();

    if (tid < BB) {
        int bb = tid;
        float l[EE]; float mx = -1e30f;
        #pragma unroll
        for (int i = 0; i < EE; ++i) { l[i] = dots[bb * EE + i]; mx = fmaxf(mx, l[i]); }
        float sum = 0.f;
        #pragma unroll
        for (int i = 0; i < EE; ++i) { l[i] = expf(l[i] - mx); sum += l[i]; }
        int i0 = 0;
        #pragma unroll
        for (int i = 1; i < EE; ++i) if (l[i] > l[i0]) i0 = i;   // ties -> lowest idx (jax)
        int i1 = (i0 == 0) ? 1 : 0;
        #pragma unroll
        for (int i = 0; i < EE; ++i) if (i != i0 && l[i] > l[i1]) i1 = i;
        g_idx[bb * 2] = i0;  g_idx[bb * 2 + 1] = i1;
        float f = LSCALE / sum;
        g_coef[bb * 2]     = l[i0] * f;
        g_coef[bb * 2 + 1] = l[i1] * f;
    }
}

// ------------------------------------------------------------------
// K3: out[b,s,:] = c0*B_{e0} + c1*B_{e1}.  B register-resident per
// thread, 32 tokens per block, coalesced float4 stores. Write-bound.
// ------------------------------------------------------------------
#define TC 32
__global__ void __launch_bounds__(256) k3_out(const float* __restrict__ lora_B,
                                              float* __restrict__ out) {
    __shared__ float c0s[TC], c1s[TC];
    const int tid = threadIdx.x;
    const int b = blockIdx.x >> 7;                 // 128 blocks per batch
    const int tokbase = (blockIdx.x & 127) * TC;
    const int e0 = g_idx[b * 2], e1 = g_idx[b * 2 + 1];
    const float w0 = g_coef[b * 2], w1 = g_coef[b * 2 + 1];

    if (tid < TC) {
        size_t gt = (size_t)b * SSEQ + tokbase + tid;
        c0s[tid] = w0 * g_h[gt * EE + e0];
        c1s[tid] = w1 * g_h[gt * EE + e1];
    }
    float4 B0 = *(const float4*)&lora_B[e0 * OUTD + tid * 4];
    float4 B1 = *(const float4*)&lora_B[e1 * OUTD + tid * 4];
    __syncthreads();

    float4* ob = (float4*)out + ((size_t)b * SSEQ + tokbase) * (OUTD / 4) + tid;
    #pragma unroll 4
    for (int i = 0; i < TC; ++i) {
        float c0 = c0s[i], c1 = c1s[i];
        float4 v;
        v.x = c0 * B0.x + c1 * B1.x;
        v.y = c0 * B0.y + c1 * B1.y;
        v.z = c0 * B0.z + c1 * B1.z;
        v.w = c0 * B0.w + c1 * B1.w;
        ob[(size_t)i * (OUTD / 4)] = v;
    }
}

// ------------------------------------------------------------------
extern "C" void kernel_launch(void* const* d_in, const int* in_sizes, int n_in,
                              void* d_out, int out_size) {
    const float* x      = (const float*)d_in[0];
    const float* lora_A = (const float*)d_in[1];
    const float* lora_B = (const float*)d_in[2];
    const float* gate_w = (const float*)d_in[3];
    const float* gate_b = (const float*)d_in[4];
    float* out = (float*)d_out;

    k0_zero<<<(BB * IND + 255) / 256, 256>>>();
    k1_dots<<<BB * (SSEQ / TT), 256>>>(x, lora_A);
    k2_gate<<<1, 1024>>>(gate_w, gate_b);
    k3_out<<<BB * (SSEQ / TC), 256>>>(lora_B, out);
}

// round 2
// speedup vs baseline: 1.0876x; 1.0876x over previous
#include <cuda_runtime.h>
#include <math.h>

#define BB    4
#define SSEQ  4096
#define IND   1024
#define OUTD  1024
#define EE    8
#define LSCALE 512.0f

// ---- scratch (device globals; allocation is forbidden) ----
__device__ float g_seg[BB * IND];               // 16 KB : per-batch column sums of x
__device__ float g_h[(size_t)BB * SSEQ * EE];   // 512 KB: all-expert dots (L2 resident)
__device__ float g_coef[BB * 2];
__device__ int   g_idx[BB * 2];

typedef unsigned long long u64;

// packed fp32x2 FMA / ADD (sm_103a; only reachable via PTX)
__device__ __forceinline__ void fma2(u64& d, u64 a, u64 b) {
    asm("fma.rn.f32x2 %0, %1, %2, %0;" : "+l"(d) : "l"(a), "l"(b));
}
__device__ __forceinline__ void add2(u64& d, u64 a) {
    asm("add.rn.f32x2 %0, %0, %1;" : "+l"(d) : "l"(a));
}
__device__ __forceinline__ float lo2(u64 v) { return __uint_as_float((unsigned)(v & 0xffffffffull)); }
__device__ __forceinline__ float hi2(u64 v) { return __uint_as_float((unsigned)(v >> 32)); }

// ------------------------------------------------------------------
// K1: h[b,s,e] = x[b,s,:]·A_e (8 experts) + per-batch column sums.
// grid = 512 blocks (128/batch), 256 thr. Warp owns 4 tokens; lane
// owns 4 consecutive k per 128-chunk. x: direct coalesced LDG.128.
// A: staged once to shared [e][k], conflict-free float4 reads.
// Math: packed f32x2 FMAs over k-pairs.
// ------------------------------------------------------------------
#define TPW  4      // tokens per warp
#define TOKB 32     // tokens per block

extern __shared__ float s_dyn[];

__global__ void __launch_bounds__(256, 2) k1_dots(const float* __restrict__ x,
                                                  const float* __restrict__ lora_A) {
    float* A_s  = s_dyn;          // 8192 floats (32 KB), [e][1024]
    float* segp = s_dyn + 8192;   // 8192 floats (32 KB), [warp][1024]

    const int tid  = threadIdx.x;
    const int w    = tid >> 5;
    const int lane = tid & 31;
    const int b       = blockIdx.x >> 7;           // 128 blocks per batch
    const int tokbase = (blockIdx.x & 127) * TOKB;

    // stage A once (contiguous copy, conflict-free)
    #pragma unroll
    for (int j = 0; j < 8; ++j) {
        int i4 = tid + j * 256;                    // 2048 float4 total
        ((float4*)A_s)[i4] = ((const float4*)lora_A)[i4];
    }
    __syncthreads();

    u64 acc[TPW][EE];
    #pragma unroll
    for (int i = 0; i < TPW; ++i)
        #pragma unroll
        for (int e = 0; e < EE; ++e) acc[i][e] = 0ull;

    const float* xw = x + ((size_t)(b * SSEQ + tokbase + w * TPW)) * IND;

    #pragma unroll
    for (int c = 0; c < 8; ++c) {                  // 8 k-chunks of 128
        const int koff = c * 128 + lane * 4;

        // x for this warp's 4 tokens (coalesced LDG.128 each)
        u64 xlo[TPW], xhi[TPW];
        u64 seglo = 0ull, seghi = 0ull;
        #pragma unroll
        for (int i = 0; i < TPW; ++i) {
            double2 xv = *(const double2*)(xw + (size_t)i * IND + koff);
            xlo[i] = __double_as_longlong(xv.x);
            xhi[i] = __double_as_longlong(xv.y);
            add2(seglo, xlo[i]);
            add2(seghi, xhi[i]);
        }

        // 8 experts, A float4 from shared (conflict-free, 2 live regs)
        #pragma unroll
        for (int e = 0; e < EE; ++e) {
            double2 av = *(const double2*)&A_s[e * IND + koff];
            u64 alo = __double_as_longlong(av.x);
            u64 ahi = __double_as_longlong(av.y);
            #pragma unroll
            for (int i = 0; i < TPW; ++i) {
                fma2(acc[i][e], xlo[i], alo);
                fma2(acc[i][e], xhi[i], ahi);
            }
        }

        // flush this chunk's seg partial (each slot written exactly once)
        double2 sv;
        sv.x = __longlong_as_double(seglo);
        sv.y = __longlong_as_double(seghi);
        *(double2*)&segp[w * IND + koff] = sv;
    }

    // ---- per-token cross-lane reduction (butterfly) + h store ----
    #pragma unroll
    for (int i = 0; i < TPW; ++i) {
        float v[EE];
        #pragma unroll
        for (int e = 0; e < EE; ++e) v[e] = lo2(acc[i][e]) + hi2(acc[i][e]);
        #pragma unroll
        for (int off = 16; off; off >>= 1)
            #pragma unroll
            for (int e = 0; e < EE; ++e)
                v[e] += __shfl_xor_sync(0xffffffffu, v[e], off);
        if (lane == 0) {
            size_t gt = (size_t)b * SSEQ + tokbase + w * TPW + i;
            *(float4*)&g_h[gt * EE]     = make_float4(v[0], v[1], v[2], v[3]);
            *(float4*)&g_h[gt * EE + 4] = make_float4(v[4], v[5], v[6], v[7]);
        }
    }

    // ---- cross-warp seg reduction + one REDG per column ----
    __syncthreads();
    {
        float4 s = ((float4*)segp)[tid];           // warp 0's row
        #pragma unroll
        for (int ww = 1; ww < 8; ++ww) {
            float4 t = *(float4*)&segp[ww * IND + tid * 4];
            s.x += t.x; s.y += t.y; s.z += t.z; s.w += t.w;
        }
        float* dst = &g_seg[b * IND + tid * 4];
        atomicAdd(dst + 0, s.x);
        atomicAdd(dst + 1, s.y);
        atomicAdd(dst + 2, s.z);
        atomicAdd(dst + 3, s.w);
    }
}

// ------------------------------------------------------------------
// K2: logits = seg_mean·G^T + b ; softmax ; top-2 ; coef = 512*w.
// Also re-zeroes g_seg for the next graph replay (k0 eliminated).
// ------------------------------------------------------------------
__global__ void k2_gate(const float* __restrict__ gate_w,
                        const float* __restrict__ gate_b) {
    __shared__ float dots[BB * EE];
    int tid = threadIdx.x;                  // 1024 threads
    int pair = tid >> 5, lane = tid & 31;   // 32 (b,e) pairs, one warp each
    int b = pair >> 3, e = pair & 7;

    float s = 0.f;
    for (int k = lane * 4; k < IND; k += 128) {
        float4 a = *(const float4*)&g_seg[b * IND + k];
        float4 g = *(const float4*)&gate_w[e * IND + k];
        s += a.x * g.x + a.y * g.y + a.z * g.z + a.w * g.w;
    }
    #pragma unroll
    for (int o = 16; o; o >>= 1) s += __shfl_xor_sync(0xffffffffu, s, o);
    if (lane == 0) dots[pair] = s * (1.0f / (float)SSEQ) + gate_b[e];
    __syncthreads();

    // zero g_seg for next replay (4096 floats = 1024 float4, one each)
    ((float4*)g_seg)[tid] = make_float4(0.f, 0.f, 0.f, 0.f);

    if (tid < BB) {
        int bb = tid;
        float l[EE]; float mx = -1e30f;
        #pragma unroll
        for (int i = 0; i < EE; ++i) { l[i] = dots[bb * EE + i]; mx = fmaxf(mx, l[i]); }
        float sum = 0.f;
        #pragma unroll
        for (int i = 0; i < EE; ++i) { l[i] = expf(l[i] - mx); sum += l[i]; }
        int i0 = 0;
        #pragma unroll
        for (int i = 1; i < EE; ++i) if (l[i] > l[i0]) i0 = i;     // ties -> lowest idx
        int i1 = (i0 == 0) ? 1 : 0;
        #pragma unroll
        for (int i = 0; i < EE; ++i) if (i != i0 && l[i] > l[i1]) i1 = i;
        g_idx[bb * 2] = i0;  g_idx[bb * 2 + 1] = i1;
        float f = LSCALE / sum;
        g_coef[bb * 2]     = l[i0] * f;
        g_coef[bb * 2 + 1] = l[i1] * f;
    }
}

// ------------------------------------------------------------------
// K3: out[b,s,:] = c0*B_{e0} + c1*B_{e1}. Fully unrolled: 32
// independent LDS(broadcast)->FFMA->STG.128 chains per thread.
// ------------------------------------------------------------------
#define TC 32
__global__ void __launch_bounds__(256) k3_out(const float* __restrict__ lora_B,
                                              float* __restrict__ out) {
    __shared__ float2 cs[TC];
    const int tid = threadIdx.x;
    const int b = blockIdx.x >> 7;                 // 128 blocks per batch
    const int tokbase = (blockIdx.x & 127) * TC;
    const int e0 = g_idx[b * 2], e1 = g_idx[b * 2 + 1];
    const float w0 = g_coef[b * 2], w1 = g_coef[b * 2 + 1];

    if (tid < TC) {
        size_t gt = (size_t)b * SSEQ + tokbase + tid;
        cs[tid] = make_float2(w0 * g_h[gt * EE + e0], w1 * g_h[gt * EE + e1]);
    }
    float4 B0 = *(const float4*)&lora_B[e0 * OUTD + tid * 4];
    float4 B1 = *(const float4*)&lora_B[e1 * OUTD + tid * 4];
    __syncthreads();

    float4* ob = (float4*)out + ((size_t)b * SSEQ + tokbase) * (OUTD / 4) + tid;
    #pragma unroll
    for (int i = 0; i < TC; ++i) {
        float2 cc = cs[i];
        float4 v;
        v.x = cc.x * B0.x + cc.y * B1.x;
        v.y = cc.x * B0.y + cc.y * B1.y;
        v.z = cc.x * B0.z + cc.y * B1.z;
        v.w = cc.x * B0.w + cc.y * B1.w;
        ob[(size_t)i * (OUTD / 4)] = v;
    }
}

// ------------------------------------------------------------------
extern "C" void kernel_launch(void* const* d_in, const int* in_sizes, int n_in,
                              void* d_out, int out_size) {
    const float* x      = (const float*)d_in[0];
    const float* lora_A = (const float*)d_in[1];
    const float* lora_B = (const float*)d_in[2];
    const float* gate_w = (const float*)d_in[3];
    const float* gate_b = (const float*)d_in[4];
    float* out = (float*)d_out;

    static bool attr_set = false;
    if (!attr_set) {
        cudaFuncSetAttribute(k1_dots, cudaFuncAttributeMaxDynamicSharedMemorySize, 65536);
        attr_set = true;
    }

    k1_dots<<<BB * (SSEQ / TOKB), 256, 65536>>>(x, lora_A);
    k2_gate<<<1, 1024>>>(gate_w, gate_b);
    k3_out<<<BB * (SSEQ / TC), 256>>>(lora_B, out);
}